// round 1
// baseline (speedup 1.0000x reference)
#include <cuda_runtime.h>
#include <cfloat>

#define BB 8
#define CC 64
#define NN 2048
#define MM 2048
#define KSEL 614           // int(2048 * 0.3)
#define NSPLIT 8

// ---------------- device scratch (static, allowed) ----------------
__device__ float g_pd[(size_t)BB * NN * MM];          // 134 MB
__device__ float g_xx[BB * NN];
__device__ float g_yy[BB * MM];
__device__ float g_rowmax[BB * NN];
__device__ float g_rowinvZ[BB * NN];
__device__ float g_colmax[BB * MM];
__device__ float g_colinvZ[BB * MM];
__device__ float g_colSum[BB * MM];                   // scoresColSum
__device__ float g_rowSum[BB * NN];                   // scoresRowSum
__device__ unsigned char g_maskSrc[BB * NN];
__device__ unsigned char g_maskTgt[BB * MM];
__device__ float g_pmax[NSPLIT * BB * MM];
__device__ float g_pz[NSPLIT * BB * MM];
__device__ float g_ps[NSPLIT * BB * MM];
__device__ float g_valInlier[BB * NN];

// ---------------- squared norms ----------------
__global__ void sqnorm_kernel(const float* __restrict__ emb, int which) {
    int idx = blockIdx.x * blockDim.x + threadIdx.x;
    if (idx >= BB * 2048) return;
    int b = idx >> 11, p = idx & 2047;
    const float* e = emb + (size_t)b * CC * 2048 + p;
    float s = 0.f;
#pragma unroll
    for (int c = 0; c < CC; c++) { float v = e[(size_t)c * 2048]; s += v * v; }
    if (which) g_yy[idx] = s; else g_xx[idx] = s;
}

// ---------------- GEMM: pd = 2*src^T*tgt - xx - yy ----------------
__global__ __launch_bounds__(256) void gemm_pd_kernel(const float* __restrict__ src,
                                                      const float* __restrict__ tgt) {
    __shared__ float As[16][64];
    __shared__ float Bs[16][64];
    int b = blockIdx.z;
    int n0 = blockIdx.y * 64, m0 = blockIdx.x * 64;
    int tid = threadIdx.x;
    int tx = tid & 15, ty = tid >> 4;
    const float* S = src + (size_t)b * CC * NN;
    const float* T = tgt + (size_t)b * CC * MM;
    float acc[4][4];
#pragma unroll
    for (int j = 0; j < 4; j++)
#pragma unroll
        for (int i = 0; i < 4; i++) acc[j][i] = 0.f;

    for (int kk = 0; kk < CC; kk += 16) {
#pragma unroll
        for (int l = tid; l < 16 * 64; l += 256) {
            int k = l >> 6, i = l & 63;
            As[k][i] = S[(size_t)(kk + k) * NN + n0 + i];
            Bs[k][i] = T[(size_t)(kk + k) * MM + m0 + i];
        }
        __syncthreads();
#pragma unroll
        for (int k = 0; k < 16; k++) {
            float a[4], bb[4];
#pragma unroll
            for (int j = 0; j < 4; j++) a[j] = As[k][ty * 4 + j];
#pragma unroll
            for (int i = 0; i < 4; i++) bb[i] = Bs[k][tx * 4 + i];
#pragma unroll
            for (int j = 0; j < 4; j++)
#pragma unroll
                for (int i = 0; i < 4; i++) acc[j][i] += a[j] * bb[i];
        }
        __syncthreads();
    }
#pragma unroll
    for (int j = 0; j < 4; j++) {
        int n = n0 + ty * 4 + j;
        float x = g_xx[b * NN + n];
        float* prow = g_pd + (size_t)(b * NN + n) * MM;
#pragma unroll
        for (int i = 0; i < 4; i++) {
            int m = m0 + tx * 4 + i;
            prow[m] = 2.f * acc[j][i] - x - g_yy[b * MM + m];
        }
    }
}

// ---------------- row softmax stats ----------------
__global__ __launch_bounds__(256) void row_stats_kernel() {
    __shared__ float sm[256];
    int row = blockIdx.x;
    int tid = threadIdx.x;
    const float* p = g_pd + (size_t)row * MM;
    float v[8];
    float mx = -FLT_MAX;
#pragma unroll
    for (int i = 0; i < 8; i++) { v[i] = p[tid + i * 256]; mx = fmaxf(mx, v[i]); }
    sm[tid] = mx; __syncthreads();
    for (int s = 128; s > 0; s >>= 1) { if (tid < s) sm[tid] = fmaxf(sm[tid], sm[tid + s]); __syncthreads(); }
    mx = sm[0]; __syncthreads();
    float su = 0.f;
#pragma unroll
    for (int i = 0; i < 8; i++) su += __expf(v[i] - mx);
    sm[tid] = su; __syncthreads();
    for (int s = 128; s > 0; s >>= 1) { if (tid < s) sm[tid] += sm[tid + s]; __syncthreads(); }
    if (tid == 0) { g_rowmax[row] = mx; g_rowinvZ[row] = 1.f / sm[0]; }
}

// ---------------- fused column pass (partials over N-chunks) ----------------
__global__ __launch_bounds__(256) void col_pass_kernel() {
    int b = blockIdx.y, z = blockIdx.z;
    int m = blockIdx.x * 256 + threadIdx.x;
    int n0 = z * (NN / NSPLIT);
    const float* p = g_pd + ((size_t)b * NN + n0) * MM + m;
    const float* rm = g_rowmax + b * NN + n0;
    const float* riz = g_rowinvZ + b * NN + n0;
    float cm = -FLT_MAX, cz = 0.f, cs = 0.f;
#pragma unroll 4
    for (int n = 0; n < NN / NSPLIT; n++) {
        float v = p[(size_t)n * MM];
        float old = cm;
        cm = fmaxf(cm, v);
        cz = cz * __expf(old - cm) + __expf(v - cm);
        cs += __expf(v - rm[n]) * riz[n];
    }
    int idx = z * (BB * MM) + b * MM + m;
    g_pmax[idx] = cm; g_pz[idx] = cz; g_ps[idx] = cs;
}

__global__ void col_merge_kernel() {
    int idx = blockIdx.x * blockDim.x + threadIdx.x;
    if (idx >= BB * MM) return;
    float gm = -FLT_MAX;
#pragma unroll
    for (int z = 0; z < NSPLIT; z++) gm = fmaxf(gm, g_pmax[z * (BB * MM) + idx]);
    float Z = 0.f, S = 0.f;
#pragma unroll
    for (int z = 0; z < NSPLIT; z++) {
        Z += g_pz[z * (BB * MM) + idx] * __expf(g_pmax[z * (BB * MM) + idx] - gm);
        S += g_ps[z * (BB * MM) + idx];
    }
    g_colmax[idx] = gm; g_colinvZ[idx] = 1.f / Z; g_colSum[idx] = S;
}

// ---------------- scoresRowSum (sum over m of column softmax) ----------------
__global__ __launch_bounds__(256) void row_sum_kernel() {
    __shared__ float sm[256];
    int row = blockIdx.x;
    int b = row >> 11;
    int tid = threadIdx.x;
    const float* p = g_pd + (size_t)row * MM;
    const float* cmax = g_colmax + b * MM;
    const float* ciz = g_colinvZ + b * MM;
    float s = 0.f;
#pragma unroll
    for (int i = 0; i < 8; i++) {
        int m = tid + i * 256;
        s += __expf(p[m] - cmax[m]) * ciz[m];
    }
    sm[tid] = s; __syncthreads();
    for (int st = 128; st > 0; st >>= 1) { if (tid < st) sm[tid] += sm[tid + st]; __syncthreads(); }
    if (tid == 0) g_rowSum[row] = sm[0];
}

// ---------------- per-batch k-th smallest via bitonic sort + mask ----------------
__global__ __launch_bounds__(256) void thresh_kernel(int which, float* __restrict__ maskOutF) {
    __shared__ float s[2048];
    int b = blockIdx.x, tid = threadIdx.x;
    const float* vals = which ? (g_rowSum + b * 2048) : (g_colSum + b * 2048);
    unsigned char* mb = which ? (g_maskSrc + b * 2048) : (g_maskTgt + b * 2048);
    for (int i = tid; i < 2048; i += 256) s[i] = vals[i];
    __syncthreads();
    for (int k = 2; k <= 2048; k <<= 1) {
        for (int j = k >> 1; j > 0; j >>= 1) {
            for (int t = tid; t < 2048; t += 256) {
                int ixj = t ^ j;
                if (ixj > t) {
                    float a = s[t], c = s[ixj];
                    bool up = ((t & k) == 0);
                    if (up ? (a > c) : (a < c)) { s[t] = c; s[ixj] = a; }
                }
            }
            __syncthreads();
        }
    }
    float thresh = s[KSEL - 1];
    for (int i = tid; i < 2048; i += 256) {
        bool mk = vals[i] < thresh;
        mb[i] = (unsigned char)mk;
        maskOutF[b * 2048 + i] = mk ? 1.0f : 0.0f;
    }
}

// ---------------- final row pass: sparse weights, src_corr, val_sum ----------------
__global__ __launch_bounds__(256) void final_row_kernel(const float* __restrict__ tgt,
                                                        float* __restrict__ outCorr) {
    __shared__ float sm[4][256];
    int row = blockIdx.x;
    int b = row >> 11, n = row & 2047;
    int tid = threadIdx.x;
    const float* p = g_pd + (size_t)row * MM;
    float rm = g_rowmax[row], riz = g_rowinvZ[row];
    int msrc = g_maskSrc[row];
    const unsigned char* mtgt = g_maskTgt + b * MM;
    const float* t0 = tgt + (size_t)b * 3 * MM;
    float cs = 0.f, d0 = 0.f, d1 = 0.f, d2 = 0.f;
#pragma unroll
    for (int i = 0; i < 8; i++) {
        int m = tid + i * 256;
        float v = p[m];
        float e = __expf(v - rm);
        float sc = e * riz;
        bool keep = msrc || mtgt[m] || (e >= 1.0f);
        if (keep) {
            cs += sc;
            d0 += sc * t0[m];
            d1 += sc * t0[MM + m];
            d2 += sc * t0[2 * MM + m];
        }
    }
    sm[0][tid] = cs; sm[1][tid] = d0; sm[2][tid] = d1; sm[3][tid] = d2;
    __syncthreads();
    for (int s = 128; s > 0; s >>= 1) {
        if (tid < s) {
            sm[0][tid] += sm[0][tid + s];
            sm[1][tid] += sm[1][tid + s];
            sm[2][tid] += sm[2][tid + s];
            sm[3][tid] += sm[3][tid + s];
        }
        __syncthreads();
    }
    if (tid == 0) {
        float colsum = sm[0][0];
        float denom = colsum < 1e-5f ? 1e-5f : colsum;
        float inv = 1.f / denom;
        outCorr[(size_t)(b * 3 + 0) * NN + n] = sm[1][0] * inv;
        outCorr[(size_t)(b * 3 + 1) * NN + n] = sm[2][0] * inv;
        outCorr[(size_t)(b * 3 + 2) * NN + n] = sm[3][0] * inv;
        float vs = colsum * inv;
        g_valInlier[row] = msrc ? 0.f : vs;
    }
}

// ---------------- src_weight normalize ----------------
__global__ __launch_bounds__(256) void src_weight_kernel(float* __restrict__ outW) {
    __shared__ float sm[256];
    int b = blockIdx.x, tid = threadIdx.x;
    float s = 0.f;
    for (int i = tid; i < 2048; i += 256) s += g_valInlier[b * 2048 + i];
    sm[tid] = s; __syncthreads();
    for (int st = 128; st > 0; st >>= 1) { if (tid < st) sm[tid] += sm[tid + st]; __syncthreads(); }
    float inv = 1.f / sm[0];
    for (int i = tid; i < 2048; i += 256) outW[b * 2048 + i] = g_valInlier[b * 2048 + i] * inv;
}

// ---------------- launch ----------------
extern "C" void kernel_launch(void* const* d_in, const int* in_sizes, int n_in,
                              void* d_out, int out_size) {
    const float* src_emb = (const float*)d_in[0];
    const float* tgt_emb = (const float*)d_in[1];
    // const float* src = (const float*)d_in[2];  // unused by reference outputs
    const float* tgt = (const float*)d_in[3];

    float* out = (float*)d_out;
    float* outCorr    = out;                       // [B,3,N] = 49152
    float* outW       = out + BB * 3 * NN;         // [B,N]   = 16384
    float* outMaskSrc = outW + BB * NN;            // [B,N]   = 16384
    float* outMaskTgt = outMaskSrc + BB * NN;      // [B,M]   = 16384

    sqnorm_kernel<<<(BB * NN + 255) / 256, 256>>>(src_emb, 0);
    sqnorm_kernel<<<(BB * MM + 255) / 256, 256>>>(tgt_emb, 1);

    gemm_pd_kernel<<<dim3(MM / 64, NN / 64, BB), 256>>>(src_emb, tgt_emb);

    row_stats_kernel<<<BB * NN, 256>>>();

    col_pass_kernel<<<dim3(MM / 256, BB, NSPLIT), 256>>>();
    col_merge_kernel<<<(BB * MM + 255) / 256, 256>>>();

    row_sum_kernel<<<BB * NN, 256>>>();

    thresh_kernel<<<BB, 256>>>(0, outMaskTgt);   // columns -> mask_tgt
    thresh_kernel<<<BB, 256>>>(1, outMaskSrc);   // rows    -> mask_src

    final_row_kernel<<<BB * NN, 256>>>(tgt, outCorr);

    src_weight_kernel<<<BB, 256>>>(outW);
}

// round 3
// speedup vs baseline: 1.1286x; 1.1286x over previous
#include <cuda_runtime.h>
#include <cfloat>

#define BB 8
#define CC 64
#define NN 2048
#define MM 2048
#define KSEL 614           // int(2048 * 0.3)

typedef unsigned long long ull;

// ---------------- device scratch ----------------
__device__ float g_pd[(size_t)BB * NN * MM];          // 134 MB
__device__ float g_xx[BB * NN];
__device__ float g_yy[BB * MM];
__device__ float g_rowp_m[16 * BB * NN];              // row stat partials (16 m-tiles)
__device__ float g_rowp_z[16 * BB * NN];
__device__ float g_colp_m[32 * BB * MM];              // col stat partials (32 n-tiles)
__device__ float g_colp_z[32 * BB * MM];
__device__ float g_rowmax[BB * NN];
__device__ float g_rowinvZ[BB * NN];
__device__ float g_colmax[BB * MM];
__device__ float g_colinvZ[BB * MM];
__device__ float g_csp[16 * BB * MM];                 // colSum partials (16 row-tiles)
__device__ float g_rsp[2 * BB * NN];                  // rowSum partials (2 col-tiles)
__device__ float g_colSum[BB * MM];
__device__ float g_rowSum[BB * NN];
__device__ unsigned char g_maskSrc[BB * NN];
__device__ unsigned char g_maskTgt[BB * MM];
__device__ float g_valInlier[BB * NN];

// ---------------- f32x2 helpers ----------------
__device__ __forceinline__ ull pack2(float x, float y) {
    ull r; asm("mov.b64 %0, {%1, %2};" : "=l"(r) : "f"(x), "f"(y)); return r;
}
__device__ __forceinline__ float2 unpack2(ull v) {
    float2 r; asm("mov.b64 {%0, %1}, %2;" : "=f"(r.x), "=f"(r.y) : "l"(v)); return r;
}
#define FMA2(d, a, b) asm("fma.rn.f32x2 %0, %1, %2, %0;" : "+l"(d) : "l"(a), "l"(b))

// ---------------- squared norms ----------------
__global__ void sqnorm_kernel(const float* __restrict__ emb, int which) {
    int idx = blockIdx.x * blockDim.x + threadIdx.x;
    if (idx >= BB * 2048) return;
    int b = idx >> 11, p = idx & 2047;
    const float* e = emb + (size_t)b * CC * 2048 + p;
    float s = 0.f;
#pragma unroll
    for (int c = 0; c < CC; c++) { float v = e[(size_t)c * 2048]; s += v * v; }
    if (which) g_yy[idx] = s; else g_xx[idx] = s;
}

// ---------------- GEMM: pd = 2*src^T*tgt - xx - yy, fused softmax stat partials ----
// block tile: 64 rows (n) x 128 cols (m). 256 threads: tx=tid&15 (col groups), ty=tid>>4 (rows)
// thread owns rows n0+ty*4+{0..3}, cols {m0+tx*4+0..3, m0+64+tx*4+0..3}
__global__ __launch_bounds__(256) void gemm_pd_kernel(const float* __restrict__ src,
                                                      const float* __restrict__ tgt) {
    __shared__ __align__(16) char sbuf[16384];
    ull   (*As2)[64]   = (ull(*)[64])sbuf;                 // 16x64 ull = 8KB (A duplicated pairs)
    float (*Bs)[128]   = (float(*)[128])(sbuf + 8192);     // 16x128 = 8KB
    float (*red_m)[128] = (float(*)[128])sbuf;             // epilogue reuse
    float (*red_z)[128] = (float(*)[128])(sbuf + 8192);

    int b = blockIdx.z;
    int n0 = blockIdx.y * 64, m0 = blockIdx.x * 128;
    int tid = threadIdx.x;
    int tx = tid & 15, ty = tid >> 4;
    const float* S = src + (size_t)b * CC * NN;
    const float* T = tgt + (size_t)b * CC * MM;

    ull acc[4][4];
#pragma unroll
    for (int j = 0; j < 4; j++)
#pragma unroll
        for (int i = 0; i < 4; i++) acc[j][i] = 0ull;

    for (int kk = 0; kk < CC; kk += 16) {
        {
            int ka = tid >> 4, na = (tid & 15) * 4;
            float4 a4 = *(const float4*)&S[(size_t)(kk + ka) * NN + n0 + na];
            As2[ka][na + 0] = pack2(a4.x, a4.x);
            As2[ka][na + 1] = pack2(a4.y, a4.y);
            As2[ka][na + 2] = pack2(a4.z, a4.z);
            As2[ka][na + 3] = pack2(a4.w, a4.w);
            int kb = tid >> 5, mmb = (tid & 31) * 4;
            *(float4*)&Bs[kb][mmb]     = *(const float4*)&T[(size_t)(kk + kb) * MM + m0 + mmb];
            *(float4*)&Bs[kb + 8][mmb] = *(const float4*)&T[(size_t)(kk + kb + 8) * MM + m0 + mmb];
        }
        __syncthreads();
#pragma unroll
        for (int k = 0; k < 16; k++) {
            ulonglong2 b0 = *(const ulonglong2*)&Bs[k][tx * 4];
            ulonglong2 b1 = *(const ulonglong2*)&Bs[k][64 + tx * 4];
            ull bv0 = b0.x, bv1 = b0.y, bv2 = b1.x, bv3 = b1.y;
#pragma unroll
            for (int j = 0; j < 4; j++) {
                ull aj = As2[k][ty * 4 + j];
                FMA2(acc[j][0], aj, bv0);
                FMA2(acc[j][1], aj, bv1);
                FMA2(acc[j][2], aj, bv2);
                FMA2(acc[j][3], aj, bv3);
            }
        }
        __syncthreads();
    }

    // ---- epilogue: finalize pd, write, fused row/col softmax stat partials ----
    int cg0 = m0 + tx * 4, cg1 = m0 + 64 + tx * 4;
    float yv[8];
#pragma unroll
    for (int i = 0; i < 4; i++) {
        yv[i]     = g_yy[b * MM + cg0 + i];
        yv[4 + i] = g_yy[b * MM + cg1 + i];
    }
    float f[4][8];
#pragma unroll
    for (int j = 0; j < 4; j++) {
        int n = n0 + ty * 4 + j;
        float xv = g_xx[b * NN + n];
#pragma unroll
        for (int i = 0; i < 4; i++) {
            float2 p = unpack2(acc[j][i]);
            f[j][2 * i]     = 2.f * p.x - xv - yv[2 * i];
            f[j][2 * i + 1] = 2.f * p.y - xv - yv[2 * i + 1];
        }
        float* prow = g_pd + (size_t)(b * NN + n) * MM;
        *(float4*)&prow[cg0] = make_float4(f[j][0], f[j][1], f[j][2], f[j][3]);
        *(float4*)&prow[cg1] = make_float4(f[j][4], f[j][5], f[j][6], f[j][7]);
    }

    // row partials: reduce across tx (16 lanes, same warp)
#pragma unroll
    for (int j = 0; j < 4; j++) {
        float rmx = f[j][0];
#pragma unroll
        for (int i = 1; i < 8; i++) rmx = fmaxf(rmx, f[j][i]);
#pragma unroll
        for (int o = 1; o < 16; o <<= 1) rmx = fmaxf(rmx, __shfl_xor_sync(0xffffffffu, rmx, o));
        float rz = 0.f;
#pragma unroll
        for (int i = 0; i < 8; i++) rz += __expf(f[j][i] - rmx);
#pragma unroll
        for (int o = 1; o < 16; o <<= 1) rz += __shfl_xor_sync(0xffffffffu, rz, o);
        if (tx == 0) {
            int n = n0 + ty * 4 + j;
            g_rowp_m[blockIdx.x * (BB * NN) + b * NN + n] = rmx;
            g_rowp_z[blockIdx.x * (BB * NN) + b * NN + n] = rz;
        }
    }

    // col partials: per-thread over 4 rows, then serial merge across 16 ty via smem
#pragma unroll
    for (int c = 0; c < 8; c++) {
        int colLocal = (c < 4) ? (tx * 4 + c) : (64 + tx * 4 + (c - 4));
        float cm = f[0][c];
#pragma unroll
        for (int j = 1; j < 4; j++) cm = fmaxf(cm, f[j][c]);
        float cz = 0.f;
#pragma unroll
        for (int j = 0; j < 4; j++) cz += __expf(f[j][c] - cm);
        red_m[ty][colLocal] = cm;
        red_z[ty][colLocal] = cz;
        __syncwarp();  // cheap; full sync below
        if (c == 7) {
            __syncthreads();
            if (tid < 128) {
                float M = -FLT_MAX, Z = 0.f;
#pragma unroll
                for (int t = 0; t < 16; t++) {
                    float m2 = red_m[t][tid], z2 = red_z[t][tid];
                    float nm = fmaxf(M, m2);
                    Z = Z * __expf(M - nm) + z2 * __expf(m2 - nm);
                    M = nm;
                }
                g_colp_m[blockIdx.y * (BB * MM) + b * MM + m0 + tid] = M;
                g_colp_z[blockIdx.y * (BB * MM) + b * MM + m0 + tid] = Z;
            }
        }
    }
}

// ---------------- merge stat partials ----------------
__global__ void merge_row_kernel() {
    int idx = blockIdx.x * blockDim.x + threadIdx.x;
    if (idx >= BB * NN) return;
    float M = -FLT_MAX, Z = 0.f;
#pragma unroll
    for (int t = 0; t < 16; t++) {
        float m2 = g_rowp_m[t * (BB * NN) + idx], z2 = g_rowp_z[t * (BB * NN) + idx];
        float nm = fmaxf(M, m2);
        Z = Z * __expf(M - nm) + z2 * __expf(m2 - nm);
        M = nm;
    }
    g_rowmax[idx] = M; g_rowinvZ[idx] = 1.f / Z;
}

__global__ void merge_col_kernel() {
    int idx = blockIdx.x * blockDim.x + threadIdx.x;
    if (idx >= BB * MM) return;
    float M = -FLT_MAX, Z = 0.f;
#pragma unroll
    for (int t = 0; t < 32; t++) {
        float m2 = g_colp_m[t * (BB * MM) + idx], z2 = g_colp_z[t * (BB * MM) + idx];
        float nm = fmaxf(M, m2);
        Z = Z * __expf(M - nm) + z2 * __expf(m2 - nm);
        M = nm;
    }
    g_colmax[idx] = M; g_colinvZ[idx] = 1.f / Z;
}

// ---------------- fused colSum + rowSum pass (one read of pd) ----------------
// tile: 1024 cols x 128 rows. thread t owns 4 consecutive cols. grid: (2, 16, 8)
__global__ __launch_bounds__(256) void cs_rs_kernel() {
    __shared__ float s_rm[128], s_riz[128];
    __shared__ float rs_w[8][128];
    int b = blockIdx.z, rt = blockIdx.y, ct = blockIdx.x;
    int tid = threadIdx.x, lane = tid & 31, warp = tid >> 5;
    int m = ct * 1024 + tid * 4;
    int r0 = rt * 128;
    if (tid < 128) {
        s_rm[tid]  = g_rowmax[b * NN + r0 + tid];
        s_riz[tid] = g_rowinvZ[b * NN + r0 + tid];
    }
    float4 cmx = *(const float4*)&g_colmax[b * MM + m];
    float4 ciz = *(const float4*)&g_colinvZ[b * MM + m];
    __syncthreads();
    float cs0 = 0.f, cs1 = 0.f, cs2 = 0.f, cs3 = 0.f;
    const float* base = g_pd + ((size_t)(b * NN + r0)) * MM + m;
#pragma unroll 4
    for (int n = 0; n < 128; n++) {
        float4 v = *(const float4*)(base + (size_t)n * MM);
        float rm = s_rm[n], riz = s_riz[n];
        float e0 = __expf(v.x - rm), e1 = __expf(v.y - rm);
        float e2 = __expf(v.z - rm), e3 = __expf(v.w - rm);
        cs0 += e0 * riz; cs1 += e1 * riz; cs2 += e2 * riz; cs3 += e3 * riz;
        float r = __expf(v.x - cmx.x) * ciz.x + __expf(v.y - cmx.y) * ciz.y
                + __expf(v.z - cmx.z) * ciz.z + __expf(v.w - cmx.w) * ciz.w;
#pragma unroll
        for (int o = 16; o > 0; o >>= 1) r += __shfl_xor_sync(0xffffffffu, r, o);
        if (lane == 0) rs_w[warp][n] = r;
    }
    __syncthreads();
    *(float4*)&g_csp[rt * (BB * MM) + b * MM + m] = make_float4(cs0, cs1, cs2, cs3);
    if (tid < 128) {
        float s = 0.f;
#pragma unroll
        for (int w = 0; w < 8; w++) s += rs_w[w][tid];
        g_rsp[ct * (BB * NN) + b * NN + r0 + tid] = s;
    }
}

__global__ void merge_sums_kernel() {
    int idx = blockIdx.x * blockDim.x + threadIdx.x;
    if (idx >= BB * MM) return;
    if (blockIdx.y == 0) {
        float s = 0.f;
#pragma unroll
        for (int t = 0; t < 16; t++) s += g_csp[t * (BB * MM) + idx];
        g_colSum[idx] = s;
    } else {
        float s = g_rsp[idx] + g_rsp[BB * NN + idx];
        g_rowSum[idx] = s;
    }
}

// ---------------- per-batch k-th smallest via bitonic sort + masks ----------------
__global__ __launch_bounds__(256) void thresh_kernel(float* __restrict__ outMaskTgt,
                                                     float* __restrict__ outMaskSrc) {
    __shared__ float s[2048];
    int b = blockIdx.x, which = blockIdx.y, tid = threadIdx.x;
    const float* vals = which ? (g_rowSum + b * 2048) : (g_colSum + b * 2048);
    unsigned char* mb = which ? (g_maskSrc + b * 2048) : (g_maskTgt + b * 2048);
    float* mf = (which ? outMaskSrc : outMaskTgt) + b * 2048;
    for (int i = tid; i < 2048; i += 256) s[i] = vals[i];
    __syncthreads();
    for (int k = 2; k <= 2048; k <<= 1) {
        for (int j = k >> 1; j > 0; j >>= 1) {
            for (int t = tid; t < 2048; t += 256) {
                int ixj = t ^ j;
                if (ixj > t) {
                    float a = s[t], c = s[ixj];
                    bool up = ((t & k) == 0);
                    if (up ? (a > c) : (a < c)) { s[t] = c; s[ixj] = a; }
                }
            }
            __syncthreads();
        }
    }
    float thresh = s[KSEL - 1];
    for (int i = tid; i < 2048; i += 256) {
        bool mk = vals[i] < thresh;
        mb[i] = (unsigned char)mk;
        mf[i] = mk ? 1.0f : 0.0f;
    }
}

// ---------------- final row pass: sparse weights, src_corr, val_sum ----------------
__global__ __launch_bounds__(256) void final_row_kernel(const float* __restrict__ tgt,
                                                        float* __restrict__ outCorr) {
    __shared__ float sm[4][256];
    int row = blockIdx.x;
    int b = row >> 11, n = row & 2047;
    int tid = threadIdx.x;
    const float* p = g_pd + (size_t)row * MM;
    float rm = g_rowmax[row], riz = g_rowinvZ[row];
    int msrc = g_maskSrc[row];
    const unsigned char* mtgt = g_maskTgt + b * MM;
    const float* t0 = tgt + (size_t)b * 3 * MM;
    float cs = 0.f, d0 = 0.f, d1 = 0.f, d2 = 0.f;
    int m0 = tid * 8;
#pragma unroll
    for (int h = 0; h < 2; h++) {
        int m = m0 + h * 4;
        float4 v  = *(const float4*)(p + m);
        float4 ta = *(const float4*)(t0 + m);
        float4 tb = *(const float4*)(t0 + MM + m);
        float4 tc = *(const float4*)(t0 + 2 * MM + m);
        unsigned mk4 = *(const unsigned*)(mtgt + m);
        float vv[4]  = {v.x, v.y, v.z, v.w};
        float taa[4] = {ta.x, ta.y, ta.z, ta.w};
        float tbb[4] = {tb.x, tb.y, tb.z, tb.w};
        float tcc[4] = {tc.x, tc.y, tc.z, tc.w};
#pragma unroll
        for (int i = 0; i < 4; i++) {
            float e = __expf(vv[i] - rm);
            float sc = e * riz;
            bool keep = msrc || ((mk4 >> (8 * i)) & 1) || (e >= 1.0f);
            if (keep) {
                cs += sc;
                d0 += sc * taa[i];
                d1 += sc * tbb[i];
                d2 += sc * tcc[i];
            }
        }
    }
    sm[0][tid] = cs; sm[1][tid] = d0; sm[2][tid] = d1; sm[3][tid] = d2;
    __syncthreads();
    for (int s = 128; s > 0; s >>= 1) {
        if (tid < s) {
            sm[0][tid] += sm[0][tid + s];
            sm[1][tid] += sm[1][tid + s];
            sm[2][tid] += sm[2][tid + s];
            sm[3][tid] += sm[3][tid + s];
        }
        __syncthreads();
    }
    if (tid == 0) {
        float colsum = sm[0][0];
        float denom = colsum < 1e-5f ? 1e-5f : colsum;
        float inv = 1.f / denom;
        outCorr[(size_t)(b * 3 + 0) * NN + n] = sm[1][0] * inv;
        outCorr[(size_t)(b * 3 + 1) * NN + n] = sm[2][0] * inv;
        outCorr[(size_t)(b * 3 + 2) * NN + n] = sm[3][0] * inv;
        float vs = colsum * inv;
        g_valInlier[row] = msrc ? 0.f : vs;
    }
}

// ---------------- src_weight normalize ----------------
__global__ __launch_bounds__(256) void src_weight_kernel(float* __restrict__ outW) {
    __shared__ float sm[256];
    int b = blockIdx.x, tid = threadIdx.x;
    float s = 0.f;
    for (int i = tid; i < 2048; i += 256) s += g_valInlier[b * 2048 + i];
    sm[tid] = s; __syncthreads();
    for (int st = 128; st > 0; st >>= 1) { if (tid < st) sm[tid] += sm[tid + st]; __syncthreads(); }
    float inv = 1.f / sm[0];
    for (int i = tid; i < 2048; i += 256) outW[b * 2048 + i] = g_valInlier[b * 2048 + i] * inv;
}

// ---------------- launch ----------------
extern "C" void kernel_launch(void* const* d_in, const int* in_sizes, int n_in,
                              void* d_out, int out_size) {
    const float* src_emb = (const float*)d_in[0];
    const float* tgt_emb = (const float*)d_in[1];
    const float* tgt = (const float*)d_in[3];

    float* out = (float*)d_out;
    float* outCorr    = out;                       // [B,3,N]
    float* outW       = out + BB * 3 * NN;         // [B,N]
    float* outMaskSrc = outW + BB * NN;            // [B,N]
    float* outMaskTgt = outMaskSrc + BB * NN;      // [B,M]

    sqnorm_kernel<<<(BB * NN + 255) / 256, 256>>>(src_emb, 0);
    sqnorm_kernel<<<(BB * MM + 255) / 256, 256>>>(tgt_emb, 1);

    gemm_pd_kernel<<<dim3(MM / 128, NN / 64, BB), 256>>>(src_emb, tgt_emb);

    merge_row_kernel<<<(BB * NN + 255) / 256, 256>>>();
    merge_col_kernel<<<(BB * MM + 255) / 256, 256>>>();

    cs_rs_kernel<<<dim3(2, 16, BB), 256>>>();
    merge_sums_kernel<<<dim3((BB * MM + 255) / 256, 2), 256>>>();

    thresh_kernel<<<dim3(BB, 2), 256>>>(outMaskTgt, outMaskSrc);

    final_row_kernel<<<BB * NN, 256>>>(tgt, outCorr);

    src_weight_kernel<<<BB, 256>>>(outW);
}